// round 16
// baseline (speedup 1.0000x reference)
#include <cuda_runtime.h>
#include <cuda_bf16.h>
#include <math.h>
#include <stdint.h>

#define NN 20000        // nodes per type
#define D  256          // feature dim
#define EE 320000       // edges per relation
#define ND (NN * D)
#define CAP 96          // bucket capacity per node per group (Poisson(32) + 11 sigma)

// ---------------- scratch (device globals: no allocation allowed) ----------------
__device__ __align__(16) float g_h0[ND];      // layer1 root+agg, type 0 (fp32)
__device__ __align__(16) float g_h1[ND];      // layer1 root+agg, type 1 (fp32)
__device__ __align__(16) float g_o2[ND];      // layer2 root part, type 0 (fp32)
__device__ __align__(16) __nv_bfloat16 g_xb[3 * ND];  // bf16 copy of x
__device__ __align__(16) __nv_bfloat16 g_hb0[ND];     // bf16 relu(h0)
__device__ __align__(16) __nv_bfloat16 g_hb1[ND];     // bf16 relu(h1)
__device__ __align__(16) __nv_bfloat16 g_yb0[ND];     // bf16 transformed features
__device__ __align__(16) __nv_bfloat16 g_yb1[ND];
__device__ __align__(16) __nv_bfloat16 g_yb2[ND];
__device__ __align__(16) __nv_bfloat16 g_yb3[ND];
__device__ __align__(16) __nv_bfloat16 g_WTb[9][D * D];  // bf16 pre-transposed weights [n][k]
__device__ float g_bc1[2 * D];
__device__ float g_bc2[D];

// Bucketed edge lists: group 0 = dst-type-0 (rel0 tag0, rel2 tag1) [reused by layer 2]
//                      group 1 = dst-type-1 (rel1 tag0, rel4 tag1)
__device__ int g_cnt[2][NN];
__device__ int g_rec[2][NN * CAP];

// pack two f32 into a bf16x2 word: low = a, high = b (PTX: cvt d, hi, lo)
__device__ __forceinline__ uint32_t bfpair(float a, float b) {
    uint32_t u;
    asm("cvt.rn.bf16x2.f32 %0, %1, %2;" : "=r"(u) : "f"(b), "f"(a));
    return u;
}

// ---------------- tiny kernels ----------------
__global__ void zero_cnt_kernel(float* o) {
    int i = blockIdx.x * blockDim.x + threadIdx.x;
    if (i < 2 * NN) ((int*)g_cnt)[i] = 0;
    if (i == 0) o[0] = 0.0f;
}

// x (fp32) -> g_xb (bf16): NPLANE node-type planes starting at plane OFS
template <int OFS, int NPLANE>
__global__ void cvt_kernel(const float* __restrict__ x) {
    int i = blockIdx.x * blockDim.x + threadIdx.x;
    if (i < NPLANE * ND / 4) {
        float4 v = ((const float4*)(x + (size_t)OFS * ND))[i];
        uint2 o;
        o.x = bfpair(v.x, v.y);
        o.y = bfpair(v.z, v.w);
        ((uint2*)(g_xb + (size_t)OFS * ND))[i] = o;
    }
}

// segment s -> (rel k, group, tag):  s0:(0,0,0)  s1:(2,0,1)  s2:(1,1,0)  s3:(4,1,1)
__device__ __forceinline__ void seg_map(int s, int& k, int& grp, int& tag) {
    switch (s) {
        case 0:  k = 0; grp = 0; tag = 0; break;
        case 1:  k = 2; grp = 0; tag = 1; break;
        case 2:  k = 1; grp = 1; tag = 0; break;
        default: k = 4; grp = 1; tag = 1; break;
    }
}

// single pass: scatter edges into per-dst buckets
__global__ void fill_kernel(const int* __restrict__ edges) {
    int idx = blockIdx.x * blockDim.x + threadIdx.x;
    if (idx >= 4 * EE) return;
    int s = idx / EE, e = idx - s * EE;
    int k, grp, tag; seg_map(s, k, grp, tag);
    int src = edges[k * 2 * EE + e];
    int dst = edges[k * 2 * EE + EE + e];
    int pos = atomicAdd(&g_cnt[grp][dst], 1);
    if (pos < CAP)
        g_rec[grp][dst * CAP + pos] = (int)((unsigned)src | ((unsigned)tag << 31));
}

// Transpose (+ combine root pairs and biases) into g_WTb[9][n][k] (bf16).
__global__ void prep_kernel(const float* __restrict__ Wrel1, const float* __restrict__ brel1,
                            const float* __restrict__ Wroot1, const float* __restrict__ Wrel2,
                            const float* __restrict__ brel2, const float* __restrict__ Wroot2) {
    __shared__ float t[32][33];
    int j = blockIdx.z;
    const float* S0; const float* S1 = nullptr;
    switch (j) {
        case 0:  S0 = Wroot1;             S1 = Wroot1 + 2 * D * D; break;
        case 1:  S0 = Wroot1 + D * D;     S1 = Wroot1 + 4 * D * D; break;
        case 2:  S0 = Wrel1;              break;
        case 3:  S0 = Wrel1 + D * D;      break;
        case 4:  S0 = Wrel1 + 2 * D * D;  break;
        case 5:  S0 = Wrel1 + 4 * D * D;  break;
        case 6:  S0 = Wroot2;             S1 = Wroot2 + 2 * D * D; break;
        case 7:  S0 = Wrel2;              break;
        default: S0 = Wrel2 + 2 * D * D;  break;
    }
    int k0 = blockIdx.y * 32, n0 = blockIdx.x * 32;
    int tx = threadIdx.x, ty = threadIdx.y;     // 32 x 8
#pragma unroll
    for (int r = ty; r < 32; r += 8) {
        float v = S0[(size_t)(k0 + r) * D + n0 + tx];
        if (S1) v += S1[(size_t)(k0 + r) * D + n0 + tx];
        t[r][tx] = v;
    }
    __syncthreads();
    __nv_bfloat16* WT = g_WTb[j];
#pragma unroll
    for (int r = ty; r < 32; r += 8)
        WT[(size_t)(n0 + r) * D + k0 + tx] = __float2bfloat16_rn(t[tx][r]);

    if (blockIdx.x == 0 && blockIdx.y == 0 && j == 0) {
        int i = ty * 32 + tx;
        if (i < D) {
            g_bc1[i]     = brel1[i]         + brel1[2 * D + i];
            g_bc1[D + i] = brel1[D + i]     + brel1[4 * D + i];
            g_bc2[i]     = brel2[i]         + brel2[2 * D + i];
        }
    }
}

// ---------------- bf16 mma.sync GEMM, 4-stage cp.async + ldmatrix ----------------
#define TSTRIDE 20                        // words per SMEM row
#define TILEB   (128 * TSTRIDE * 4)       // bytes per tile buffer (10240)
#define NSTAGE  4
#define SMEM_GEMM (2 * NSTAGE * TILEB)    // 81920 bytes

__device__ __forceinline__ void cp16(uint32_t dst, const void* src, int sz) {
    asm volatile("cp.async.cg.shared.global [%0], [%1], 16, %2;"
                 :: "r"(dst), "l"(src), "r"(sz) : "memory");
}
__device__ __forceinline__ void cp_commit() {
    asm volatile("cp.async.commit_group;" ::: "memory");
}
__device__ __forceinline__ void ldm4(uint32_t& r0, uint32_t& r1, uint32_t& r2, uint32_t& r3,
                                     uint32_t addr) {
    asm volatile("ldmatrix.sync.aligned.m8n8.x4.shared.b16 {%0,%1,%2,%3}, [%4];"
                 : "=r"(r0), "=r"(r1), "=r"(r2), "=r"(r3) : "r"(addr));
}

__device__ __forceinline__ void mma_bf16(float* c, const uint32_t* a, const uint32_t* b) {
    asm volatile(
        "mma.sync.aligned.m16n8k16.row.col.f32.bf16.bf16.f32 "
        "{%0,%1,%2,%3}, {%4,%5,%6,%7}, {%8,%9}, {%0,%1,%2,%3};"
        : "+f"(c[0]), "+f"(c[1]), "+f"(c[2]), "+f"(c[3])
        : "r"(a[0]), "r"(a[1]), "r"(a[2]), "r"(a[3]), "r"(b[0]), "r"(b[1]));
}

template <bool BF16OUT>
__device__ __forceinline__ void gemm_body(const __nv_bfloat16* __restrict__ A,
                                          const __nv_bfloat16* __restrict__ WT,
                                          const float* __restrict__ bias,
                                          float* __restrict__ Cf,
                                          __nv_bfloat16* __restrict__ Cb) {
    extern __shared__ __align__(16) uint32_t smem[];
    const uint32_t sbase = (uint32_t)__cvta_generic_to_shared(smem);

    const int tid  = threadIdx.x;
    const int wid  = tid >> 5;
    const int lane = tid & 31;
    const int gid  = lane >> 2;
    const int tig  = lane & 3;
    const int m0 = blockIdx.x * 128;
    const int n0 = blockIdx.y * 128;
    const int wm = (wid & 3) * 32;
    const int wn = (wid >> 2) * 64;

    const int arow = tid >> 2;
    const int ac   = tid & 3;

    uint32_t aoff[2];
#pragma unroll
    for (int mt = 0; mt < 2; mt++) {
        int row = wm + mt * 16 + ((lane >> 3) & 1) * 8 + (lane & 7);
        aoff[mt] = (uint32_t)(row * TSTRIDE + (lane >> 4) * 4) * 4;
    }
    uint32_t boff[4];
#pragma unroll
    for (int p = 0; p < 4; p++) {
        int row = wn + p * 16 + ((lane >> 4) & 1) * 8 + (lane & 7);
        boff[p] = (uint32_t)(row * TSTRIDE + ((lane >> 3) & 1) * 4) * 4;
    }

    auto stage = [&](int kc, int b) {
        uint32_t sa = sbase + (uint32_t)b * TILEB;
        uint32_t sb = sbase + (uint32_t)(NSTAGE + b) * TILEB;
#pragma unroll
        for (int i = 0; i < 2; i++) {
            int row = arow + i * 64;
            int m = m0 + row;
            const void* src = A + (size_t)m * D + kc * 32 + ac * 8;
            cp16(sa + (uint32_t)(row * 80 + ac * 16), src, m < NN ? 16 : 0);
        }
#pragma unroll
        for (int i = 0; i < 2; i++) {
            int row = arow + i * 64;
            const void* src = WT + (size_t)(n0 + row) * D + kc * 32 + ac * 8;
            cp16(sb + (uint32_t)(row * 80 + ac * 16), src, 16);
        }
        cp_commit();
    };

    float acc[2][8][4];
#pragma unroll
    for (int mt = 0; mt < 2; mt++)
#pragma unroll
        for (int nt = 0; nt < 8; nt++)
#pragma unroll
            for (int q = 0; q < 4; q++) acc[mt][nt][q] = 0.0f;

    stage(0, 0);
    stage(1, 1);
    stage(2, 2);

    for (int kc = 0; kc < 8; kc++) {
        const int buf = kc & 3;
        if (kc < 6)      asm volatile("cp.async.wait_group 2;" ::: "memory");
        else if (kc == 6) asm volatile("cp.async.wait_group 1;" ::: "memory");
        else             asm volatile("cp.async.wait_group 0;" ::: "memory");
        __syncthreads();

        const uint32_t pa = sbase + (uint32_t)buf * TILEB;
        const uint32_t pb = sbase + (uint32_t)(NSTAGE + buf) * TILEB;
#pragma unroll
        for (int ks = 0; ks < 2; ks++) {
            const uint32_t kb = ks * 32;
            uint32_t af[2][4], bf[8][2];
#pragma unroll
            for (int mt = 0; mt < 2; mt++)
                ldm4(af[mt][0], af[mt][1], af[mt][2], af[mt][3], pa + aoff[mt] + kb);
#pragma unroll
            for (int p = 0; p < 4; p++)
                ldm4(bf[2 * p][0], bf[2 * p][1], bf[2 * p + 1][0], bf[2 * p + 1][1],
                     pb + boff[p] + kb);
#pragma unroll
            for (int mt = 0; mt < 2; mt++)
#pragma unroll
                for (int nt = 0; nt < 8; nt++)
                    mma_bf16(acc[mt][nt], af[mt], bf[nt]);
        }
        int nk = kc + 3;
        if (nk < 8) stage(nk, nk & 3);
    }

#pragma unroll
    for (int mt = 0; mt < 2; mt++) {
        int m_lo = m0 + wm + mt * 16 + gid;
        int m_hi = m_lo + 8;
#pragma unroll
        for (int nt = 0; nt < 8; nt++) {
            int n = n0 + wn + nt * 8 + tig * 2;
            if (BF16OUT) {
                if (m_lo < NN)
                    *(uint32_t*)(Cb + (size_t)m_lo * D + n) =
                        bfpair(acc[mt][nt][0], acc[mt][nt][1]);
                if (m_hi < NN)
                    *(uint32_t*)(Cb + (size_t)m_hi * D + n) =
                        bfpair(acc[mt][nt][2], acc[mt][nt][3]);
            } else {
                float b0 = bias ? bias[n] : 0.f;
                float b1 = bias ? bias[n + 1] : 0.f;
                if (m_lo < NN)
                    *(float2*)(Cf + (size_t)m_lo * D + n) =
                        make_float2(acc[mt][nt][0] + b0, acc[mt][nt][1] + b1);
                if (m_hi < NN)
                    *(float2*)(Cf + (size_t)m_hi * D + n) =
                        make_float2(acc[mt][nt][2] + b0, acc[mt][nt][3] + b1);
            }
        }
    }
}

// ---- GEMM kernels (all on the compute stream, serial) ----
// gemm1a: group-0 inputs: h0, yb0, yb1  (uses x0, x1)
__global__ __launch_bounds__(256, 2) void gemm1a_tc() {
    switch (blockIdx.z) {
        case 0:  gemm_body<false>(g_xb,      g_WTb[0], g_bc1, g_h0, nullptr); break;
        case 1:  gemm_body<true >(g_xb,      g_WTb[2], nullptr, nullptr, g_yb0); break;
        default: gemm_body<true >(g_xb + ND, g_WTb[4], nullptr, nullptr, g_yb1); break;
    }
}
// gemm1b: group-1 inputs: h1, yb2, yb3  (uses x0, x1, x2)
__global__ __launch_bounds__(256, 2) void gemm1b_tc() {
    switch (blockIdx.z) {
        case 0:  gemm_body<false>(g_xb + ND,     g_WTb[1], g_bc1 + D, g_h1, nullptr); break;
        case 1:  gemm_body<true >(g_xb,          g_WTb[3], nullptr, nullptr, g_yb2); break;
        default: gemm_body<true >(g_xb + 2 * ND, g_WTb[5], nullptr, nullptr, g_yb3); break;
    }
}
// gemm2a: o2 root + yb0' (both read hb0)
__global__ __launch_bounds__(256, 2) void gemm2a_tc() {
    if (blockIdx.z == 0) gemm_body<false>(g_hb0, g_WTb[6], g_bc2, g_o2, nullptr);
    else                 gemm_body<true >(g_hb0, g_WTb[7], nullptr, nullptr, g_yb0);
}
// gemm2b: yb1' -> g_yb2 (dead after gather1_g1; ordered by evG1)
__global__ __launch_bounds__(256, 2) void gemm2b_tc() {
    gemm_body<true>(g_hb1, g_WTb[8], nullptr, nullptr, g_yb2);
}

// ---------------- bucket gather: one warp per dst node ----------------
__device__ __forceinline__ void accum_row(float* acc, const __nv_bfloat16* __restrict__ y0,
                                          const __nv_bfloat16* __restrict__ y1,
                                          int rec, int lane) {
    const __nv_bfloat16* yb = (rec < 0) ? y1 : y0;
    int src = rec & 0x7fffffff;
    uint4 v = *(const uint4*)(yb + (size_t)src * D + lane * 8);
    const __nv_bfloat162* p = (const __nv_bfloat162*)&v;
    float2 f0 = __bfloat1622float2(p[0]);
    float2 f1 = __bfloat1622float2(p[1]);
    float2 f2 = __bfloat1622float2(p[2]);
    float2 f3 = __bfloat1622float2(p[3]);
    acc[0] += f0.x; acc[1] += f0.y; acc[2] += f1.x; acc[3] += f1.y;
    acc[4] += f2.x; acc[5] += f2.y; acc[6] += f3.x; acc[7] += f3.y;
}

__device__ __forceinline__ void gather_accum(int grp, int node,
                                             const __nv_bfloat16* __restrict__ y0,
                                             const __nv_bfloat16* __restrict__ y1,
                                             float* acc, int lane) {
    const int* __restrict__ recs = g_rec[grp] + node * CAP;
    int cnt = g_cnt[grp][node];
    if (cnt > CAP) cnt = CAP;

    for (int base = 0; base < cnt; base += 32) {
        int m = cnt - base;
        if (m > 32) m = 32;
        int rec = 0;
        if (lane < m) rec = recs[base + lane];
        int j = 0;
        for (; j + 4 <= m; j += 4) {
            int r0 = __shfl_sync(0xFFFFFFFFu, rec, j);
            int r1 = __shfl_sync(0xFFFFFFFFu, rec, j + 1);
            int r2 = __shfl_sync(0xFFFFFFFFu, rec, j + 2);
            int r3 = __shfl_sync(0xFFFFFFFFu, rec, j + 3);
            accum_row(acc, y0, y1, r0, lane);
            accum_row(acc, y0, y1, r1, lane);
            accum_row(acc, y0, y1, r2, lane);
            accum_row(acc, y0, y1, r3, lane);
        }
        for (; j < m; j++) {
            int r = __shfl_sync(0xFFFFFFFFu, rec, j);
            accum_row(acc, y0, y1, r, lane);
        }
    }
}

// layer-1 gather for ONE group: h = root + agg; write bf16 relu(h)
template <int GRP>
__device__ __forceinline__ void gather1_body() {
    int node = (blockIdx.x * blockDim.x + threadIdx.x) >> 5;   // 0..NN-1
    int lane = threadIdx.x & 31;

    float acc[8] = {0.f, 0.f, 0.f, 0.f, 0.f, 0.f, 0.f, 0.f};
    if (GRP == 0) gather_accum(0, node, g_yb0, g_yb1, acc, lane);
    else          gather_accum(1, node, g_yb2, g_yb3, acc, lane);

    const float* rootp = (GRP == 0 ? g_h0 : g_h1) + (size_t)node * D + lane * 8;
    float4 a = *(const float4*)rootp;
    float4 b = *(const float4*)(rootp + 4);
    uint4 w;
    w.x = bfpair(fmaxf(a.x + acc[0], 0.f), fmaxf(a.y + acc[1], 0.f));
    w.y = bfpair(fmaxf(a.z + acc[2], 0.f), fmaxf(a.w + acc[3], 0.f));
    w.z = bfpair(fmaxf(b.x + acc[4], 0.f), fmaxf(b.y + acc[5], 0.f));
    w.w = bfpair(fmaxf(b.z + acc[6], 0.f), fmaxf(b.w + acc[7], 0.f));
    __nv_bfloat16* hb = GRP == 0 ? g_hb0 : g_hb1;
    *(uint4*)(hb + (size_t)node * D + lane * 8) = w;
}

__global__ void gather1_g0_kernel() { gather1_body<0>(); }
__global__ void gather1_g1_kernel() { gather1_body<1>(); }

// ---------------- fused layer-2 gather + loss ----------------
// tag0 rows from g_yb0 (gemm2a), tag1 rows from g_yb2 (gemm2b)
__global__ void gather2_loss_kernel(const int* __restrict__ y, float* __restrict__ out) {
    int gw   = (blockIdx.x * blockDim.x + threadIdx.x) >> 5;   // 0..19999
    int lane = threadIdx.x & 31;

    float acc[8] = {0.f, 0.f, 0.f, 0.f, 0.f, 0.f, 0.f, 0.f};
    gather_accum(0, gw, g_yb0, g_yb2, acc, lane);

    const float* rp = g_o2 + (size_t)gw * D + lane * 8;
    float4 a = *(const float4*)rp;
    float4 b = *(const float4*)(rp + 4);
    float v[8];
    v[0] = a.x + acc[0]; v[1] = a.y + acc[1]; v[2] = a.z + acc[2]; v[3] = a.w + acc[3];
    v[4] = b.x + acc[4]; v[5] = b.y + acc[5]; v[6] = b.z + acc[6]; v[7] = b.w + acc[7];

    float m = v[0];
#pragma unroll
    for (int i = 1; i < 8; i++) m = fmaxf(m, v[i]);
#pragma unroll
    for (int o = 16; o; o >>= 1) m = fmaxf(m, __shfl_xor_sync(0xFFFFFFFFu, m, o));

    float s = 0.0f;
#pragma unroll
    for (int i = 0; i < 8; i++) s += expf(v[i] - m);
#pragma unroll
    for (int o = 16; o; o >>= 1) s += __shfl_xor_sync(0xFFFFFFFFu, s, o);

    int yy = y[gw];
    float tv = v[0];
#pragma unroll
    for (int j = 1; j < 8; j++) tv = ((yy & 7) == j) ? v[j] : tv;
    float target = __shfl_sync(0xFFFFFFFFu, tv, yy >> 3);

    float nll = (m + logf(s)) - target;

    __shared__ float partial[8];
    if (lane == 0) partial[threadIdx.x >> 5] = nll;
    __syncthreads();
    if (threadIdx.x == 0) {
        float t = 0.0f;
#pragma unroll
        for (int i = 0; i < 8; i++) t += partial[i];
        atomicAdd(out, t * (1.0f / (float)NN));
    }
}

// ---------------- launch: compute stream (s0) + memory stream (s1) ----------------
extern "C" void kernel_launch(void* const* d_in, const int* in_sizes, int n_in,
                              void* d_out, int out_size) {
    const float* x      = (const float*)d_in[0];
    const int*   edges  = (const int*)d_in[1];
    const int*   y      = (const int*)d_in[2];
    const float* Wrel1  = (const float*)d_in[3];
    const float* brel1  = (const float*)d_in[4];
    const float* Wroot1 = (const float*)d_in[5];
    const float* Wrel2  = (const float*)d_in[6];
    const float* brel2  = (const float*)d_in[7];
    const float* Wroot2 = (const float*)d_in[8];
    float* out = (float*)d_out;

    static cudaStream_t s1 = nullptr;
    static cudaEvent_t evR, evC2, evA, evB, evG0, evG1, evD, evEnd;
    if (!s1) {
        cudaStreamCreateWithFlags(&s1, cudaStreamNonBlocking);
        cudaEventCreateWithFlags(&evR,   cudaEventDisableTiming);
        cudaEventCreateWithFlags(&evC2,  cudaEventDisableTiming);
        cudaEventCreateWithFlags(&evA,   cudaEventDisableTiming);
        cudaEventCreateWithFlags(&evB,   cudaEventDisableTiming);
        cudaEventCreateWithFlags(&evG0,  cudaEventDisableTiming);
        cudaEventCreateWithFlags(&evG1,  cudaEventDisableTiming);
        cudaEventCreateWithFlags(&evD,   cudaEventDisableTiming);
        cudaEventCreateWithFlags(&evEnd, cudaEventDisableTiming);
    }
    cudaFuncSetAttribute(gemm1a_tc, cudaFuncAttributeMaxDynamicSharedMemorySize, SMEM_GEMM);
    cudaFuncSetAttribute(gemm1b_tc, cudaFuncAttributeMaxDynamicSharedMemorySize, SMEM_GEMM);
    cudaFuncSetAttribute(gemm2a_tc, cudaFuncAttributeMaxDynamicSharedMemorySize, SMEM_GEMM);
    cudaFuncSetAttribute(gemm2b_tc, cudaFuncAttributeMaxDynamicSharedMemorySize, SMEM_GEMM);

    const int MT = (NN + 127) / 128;   // 157 M-tiles
    cudaStream_t s0 = 0;

    // fork s1 from the capture origin
    cudaEventRecord(evR, s0);
    cudaStreamWaitEvent(s1, evR, 0);

    // s1 (memory): zero -> cvt_b(x2) -> fill
    zero_cnt_kernel<<<(2 * NN + 255) / 256, 256, 0, s1>>>(out);
    cvt_kernel<2, 1><<<(ND / 4 + 255) / 256, 256, 0, s1>>>(x);
    cudaEventRecord(evC2, s1);
    fill_kernel<<<(4 * EE + 255) / 256, 256, 0, s1>>>(edges);

    // s0 (compute): cvt_a(x0,x1) -> prep -> gemm1a
    cvt_kernel<0, 2><<<(2 * ND / 4 + 255) / 256, 256, 0, s0>>>(x);
    prep_kernel<<<dim3(8, 8, 9), dim3(32, 8), 0, s0>>>(Wrel1, brel1, Wroot1,
                                                       Wrel2, brel2, Wroot2);
    gemm1a_tc<<<dim3(MT, 2, 3), 256, SMEM_GEMM, s0>>>();
    cudaEventRecord(evA, s0);

    // s0: gemm1b (needs x2 from s1) — co-runs with gather1_g0 on s1
    cudaStreamWaitEvent(s0, evC2, 0);
    gemm1b_tc<<<dim3(MT, 2, 3), 256, SMEM_GEMM, s0>>>();
    cudaEventRecord(evB, s0);

    // s1: gather1_g0 (needs gemm1a + fill[s1 order])
    cudaStreamWaitEvent(s1, evA, 0);
    gather1_g0_kernel<<<(NN * 32) / 256, 256, 0, s1>>>();
    cudaEventRecord(evG0, s1);

    // s0: gemm2a (needs hb0) — co-runs with gather1_g1 on s1
    cudaStreamWaitEvent(s0, evG0, 0);
    gemm2a_tc<<<dim3(MT, 2, 2), 256, SMEM_GEMM, s0>>>();

    // s1: gather1_g1 (needs gemm1b)
    cudaStreamWaitEvent(s1, evB, 0);
    gather1_g1_kernel<<<(NN * 32) / 256, 256, 0, s1>>>();
    cudaEventRecord(evG1, s1);

    // s0: gemm2b (needs hb1; overwrites yb2 AFTER gather1_g1 read it)
    cudaStreamWaitEvent(s0, evG1, 0);
    gemm2b_tc<<<dim3(MT, 2, 1), 256, SMEM_GEMM, s0>>>();
    cudaEventRecord(evD, s0);

    // s1: fused gather + loss (needs gemm2a + gemm2b via evD [s0 order])
    cudaStreamWaitEvent(s1, evD, 0);
    gather2_loss_kernel<<<NN / 8, 256, 0, s1>>>(y, out);
    cudaEventRecord(evEnd, s1);

    // rejoin the capture origin stream
    cudaStreamWaitEvent(s0, evEnd, 0);
}

// round 17
// speedup vs baseline: 1.1044x; 1.1044x over previous
#include <cuda_runtime.h>
#include <cuda_bf16.h>
#include <math.h>
#include <stdint.h>

#define NN 20000        // nodes per type
#define D  256          // feature dim
#define EE 320000       // edges per relation
#define ND (NN * D)
#define CAP 96          // bucket capacity per node per group (Poisson(32) + 11 sigma)

// ---------------- scratch (device globals: no allocation allowed) ----------------
__device__ __align__(16) float g_h0[ND];      // layer1 root+agg, type 0 (fp32)
__device__ __align__(16) float g_h1[ND];      // layer1 root+agg, type 1 (fp32)
__device__ __align__(16) float g_o2[ND];      // layer2 root part, type 0 (fp32)
__device__ __align__(16) __nv_bfloat16 g_xb[3 * ND];  // bf16 copy of x
__device__ __align__(16) __nv_bfloat16 g_hb0[ND];     // bf16 relu(h0)
__device__ __align__(16) __nv_bfloat16 g_hb1[ND];     // bf16 relu(h1)
__device__ __align__(16) __nv_bfloat16 g_yb0[ND];     // bf16 transformed features
__device__ __align__(16) __nv_bfloat16 g_yb1[ND];
__device__ __align__(16) __nv_bfloat16 g_yb2[ND];
__device__ __align__(16) __nv_bfloat16 g_yb3[ND];
__device__ __align__(16) __nv_bfloat16 g_WTb[9][D * D];  // bf16 pre-transposed weights [n][k]
__device__ float g_bc1[2 * D];
__device__ float g_bc2[D];

// Bucketed edge lists: group 0 = dst-type-0 (rel0 tag0, rel2 tag1) [reused by layer 2]
//                      group 1 = dst-type-1 (rel1 tag0, rel4 tag1)
__device__ int g_cnt[2][NN];
__device__ int g_rec[2][NN * CAP];

// pack two f32 into a bf16x2 word: low = a, high = b (PTX: cvt d, hi, lo)
__device__ __forceinline__ uint32_t bfpair(float a, float b) {
    uint32_t u;
    asm("cvt.rn.bf16x2.f32 %0, %1, %2;" : "=r"(u) : "f"(b), "f"(a));
    return u;
}

// ---------------- tiny kernels ----------------
__global__ void zero_cnt_kernel(float* o) {
    int i = blockIdx.x * blockDim.x + threadIdx.x;
    if (i < 2 * NN) ((int*)g_cnt)[i] = 0;
    if (i == 0) o[0] = 0.0f;
}

// x (fp32) -> g_xb (bf16): NPLANE node-type planes starting at plane OFS
template <int OFS, int NPLANE>
__global__ void cvt_kernel(const float* __restrict__ x) {
    int i = blockIdx.x * blockDim.x + threadIdx.x;
    if (i < NPLANE * ND / 4) {
        float4 v = ((const float4*)(x + (size_t)OFS * ND))[i];
        uint2 o;
        o.x = bfpair(v.x, v.y);
        o.y = bfpair(v.z, v.w);
        ((uint2*)(g_xb + (size_t)OFS * ND))[i] = o;
    }
}

// segment s -> (rel k, group, tag):  s0:(0,0,0)  s1:(2,0,1)  s2:(1,1,0)  s3:(4,1,1)
__device__ __forceinline__ void seg_map(int s, int& k, int& grp, int& tag) {
    switch (s) {
        case 0:  k = 0; grp = 0; tag = 0; break;
        case 1:  k = 2; grp = 0; tag = 1; break;
        case 2:  k = 1; grp = 1; tag = 0; break;
        default: k = 4; grp = 1; tag = 1; break;
    }
}

// single pass: scatter edges into per-dst buckets
__global__ void fill_kernel(const int* __restrict__ edges) {
    int idx = blockIdx.x * blockDim.x + threadIdx.x;
    if (idx >= 4 * EE) return;
    int s = idx / EE, e = idx - s * EE;
    int k, grp, tag; seg_map(s, k, grp, tag);
    int src = edges[k * 2 * EE + e];
    int dst = edges[k * 2 * EE + EE + e];
    int pos = atomicAdd(&g_cnt[grp][dst], 1);
    if (pos < CAP)
        g_rec[grp][dst * CAP + pos] = (int)((unsigned)src | ((unsigned)tag << 31));
}

// Transpose (+ combine root pairs and biases) into g_WTb[9][n][k] (bf16).
__global__ void prep_kernel(const float* __restrict__ Wrel1, const float* __restrict__ brel1,
                            const float* __restrict__ Wroot1, const float* __restrict__ Wrel2,
                            const float* __restrict__ brel2, const float* __restrict__ Wroot2) {
    __shared__ float t[32][33];
    int j = blockIdx.z;
    const float* S0; const float* S1 = nullptr;
    switch (j) {
        case 0:  S0 = Wroot1;             S1 = Wroot1 + 2 * D * D; break;
        case 1:  S0 = Wroot1 + D * D;     S1 = Wroot1 + 4 * D * D; break;
        case 2:  S0 = Wrel1;              break;
        case 3:  S0 = Wrel1 + D * D;      break;
        case 4:  S0 = Wrel1 + 2 * D * D;  break;
        case 5:  S0 = Wrel1 + 4 * D * D;  break;
        case 6:  S0 = Wroot2;             S1 = Wroot2 + 2 * D * D; break;
        case 7:  S0 = Wrel2;              break;
        default: S0 = Wrel2 + 2 * D * D;  break;
    }
    int k0 = blockIdx.y * 32, n0 = blockIdx.x * 32;
    int tx = threadIdx.x, ty = threadIdx.y;     // 32 x 8
#pragma unroll
    for (int r = ty; r < 32; r += 8) {
        float v = S0[(size_t)(k0 + r) * D + n0 + tx];
        if (S1) v += S1[(size_t)(k0 + r) * D + n0 + tx];
        t[r][tx] = v;
    }
    __syncthreads();
    __nv_bfloat16* WT = g_WTb[j];
#pragma unroll
    for (int r = ty; r < 32; r += 8)
        WT[(size_t)(n0 + r) * D + k0 + tx] = __float2bfloat16_rn(t[tx][r]);

    if (blockIdx.x == 0 && blockIdx.y == 0 && j == 0) {
        int i = ty * 32 + tx;
        if (i < D) {
            g_bc1[i]     = brel1[i]         + brel1[2 * D + i];
            g_bc1[D + i] = brel1[D + i]     + brel1[4 * D + i];
            g_bc2[i]     = brel2[i]         + brel2[2 * D + i];
        }
    }
}

// ---------------- bf16 mma.sync GEMM, 4-stage cp.async + ldmatrix ----------------
#define TSTRIDE 20                        // words per SMEM row
#define TILEB   (128 * TSTRIDE * 4)       // bytes per tile buffer (10240)
#define NSTAGE  4
#define SMEM_GEMM (2 * NSTAGE * TILEB)    // 81920 bytes

__device__ __forceinline__ void cp16(uint32_t dst, const void* src, int sz) {
    asm volatile("cp.async.cg.shared.global [%0], [%1], 16, %2;"
                 :: "r"(dst), "l"(src), "r"(sz) : "memory");
}
__device__ __forceinline__ void cp_commit() {
    asm volatile("cp.async.commit_group;" ::: "memory");
}
__device__ __forceinline__ void ldm4(uint32_t& r0, uint32_t& r1, uint32_t& r2, uint32_t& r3,
                                     uint32_t addr) {
    asm volatile("ldmatrix.sync.aligned.m8n8.x4.shared.b16 {%0,%1,%2,%3}, [%4];"
                 : "=r"(r0), "=r"(r1), "=r"(r2), "=r"(r3) : "r"(addr));
}

__device__ __forceinline__ void mma_bf16(float* c, const uint32_t* a, const uint32_t* b) {
    asm volatile(
        "mma.sync.aligned.m16n8k16.row.col.f32.bf16.bf16.f32 "
        "{%0,%1,%2,%3}, {%4,%5,%6,%7}, {%8,%9}, {%0,%1,%2,%3};"
        : "+f"(c[0]), "+f"(c[1]), "+f"(c[2]), "+f"(c[3])
        : "r"(a[0]), "r"(a[1]), "r"(a[2]), "r"(a[3]), "r"(b[0]), "r"(b[1]));
}

template <bool BF16OUT>
__device__ __forceinline__ void gemm_body(const __nv_bfloat16* __restrict__ A,
                                          const __nv_bfloat16* __restrict__ WT,
                                          const float* __restrict__ bias,
                                          float* __restrict__ Cf,
                                          __nv_bfloat16* __restrict__ Cb) {
    extern __shared__ __align__(16) uint32_t smem[];
    const uint32_t sbase = (uint32_t)__cvta_generic_to_shared(smem);

    const int tid  = threadIdx.x;
    const int wid  = tid >> 5;
    const int lane = tid & 31;
    const int gid  = lane >> 2;
    const int tig  = lane & 3;
    const int m0 = blockIdx.x * 128;
    const int n0 = blockIdx.y * 128;
    const int wm = (wid & 3) * 32;
    const int wn = (wid >> 2) * 64;

    const int arow = tid >> 2;
    const int ac   = tid & 3;

    uint32_t aoff[2];
#pragma unroll
    for (int mt = 0; mt < 2; mt++) {
        int row = wm + mt * 16 + ((lane >> 3) & 1) * 8 + (lane & 7);
        aoff[mt] = (uint32_t)(row * TSTRIDE + (lane >> 4) * 4) * 4;
    }
    uint32_t boff[4];
#pragma unroll
    for (int p = 0; p < 4; p++) {
        int row = wn + p * 16 + ((lane >> 4) & 1) * 8 + (lane & 7);
        boff[p] = (uint32_t)(row * TSTRIDE + ((lane >> 3) & 1) * 4) * 4;
    }

    auto stage = [&](int kc, int b) {
        uint32_t sa = sbase + (uint32_t)b * TILEB;
        uint32_t sb = sbase + (uint32_t)(NSTAGE + b) * TILEB;
#pragma unroll
        for (int i = 0; i < 2; i++) {
            int row = arow + i * 64;
            int m = m0 + row;
            const void* src = A + (size_t)m * D + kc * 32 + ac * 8;
            cp16(sa + (uint32_t)(row * 80 + ac * 16), src, m < NN ? 16 : 0);
        }
#pragma unroll
        for (int i = 0; i < 2; i++) {
            int row = arow + i * 64;
            const void* src = WT + (size_t)(n0 + row) * D + kc * 32 + ac * 8;
            cp16(sb + (uint32_t)(row * 80 + ac * 16), src, 16);
        }
        cp_commit();
    };

    float acc[2][8][4];
#pragma unroll
    for (int mt = 0; mt < 2; mt++)
#pragma unroll
        for (int nt = 0; nt < 8; nt++)
#pragma unroll
            for (int q = 0; q < 4; q++) acc[mt][nt][q] = 0.0f;

    stage(0, 0);
    stage(1, 1);
    stage(2, 2);

    for (int kc = 0; kc < 8; kc++) {
        const int buf = kc & 3;
        if (kc < 6)      asm volatile("cp.async.wait_group 2;" ::: "memory");
        else if (kc == 6) asm volatile("cp.async.wait_group 1;" ::: "memory");
        else             asm volatile("cp.async.wait_group 0;" ::: "memory");
        __syncthreads();

        const uint32_t pa = sbase + (uint32_t)buf * TILEB;
        const uint32_t pb = sbase + (uint32_t)(NSTAGE + buf) * TILEB;
#pragma unroll
        for (int ks = 0; ks < 2; ks++) {
            const uint32_t kb = ks * 32;
            uint32_t af[2][4], bf[8][2];
#pragma unroll
            for (int mt = 0; mt < 2; mt++)
                ldm4(af[mt][0], af[mt][1], af[mt][2], af[mt][3], pa + aoff[mt] + kb);
#pragma unroll
            for (int p = 0; p < 4; p++)
                ldm4(bf[2 * p][0], bf[2 * p][1], bf[2 * p + 1][0], bf[2 * p + 1][1],
                     pb + boff[p] + kb);
#pragma unroll
            for (int mt = 0; mt < 2; mt++)
#pragma unroll
                for (int nt = 0; nt < 8; nt++)
                    mma_bf16(acc[mt][nt], af[mt], bf[nt]);
        }
        int nk = kc + 3;
        if (nk < 8) stage(nk, nk & 3);
    }

#pragma unroll
    for (int mt = 0; mt < 2; mt++) {
        int m_lo = m0 + wm + mt * 16 + gid;
        int m_hi = m_lo + 8;
#pragma unroll
        for (int nt = 0; nt < 8; nt++) {
            int n = n0 + wn + nt * 8 + tig * 2;
            if (BF16OUT) {
                if (m_lo < NN)
                    *(uint32_t*)(Cb + (size_t)m_lo * D + n) =
                        bfpair(acc[mt][nt][0], acc[mt][nt][1]);
                if (m_hi < NN)
                    *(uint32_t*)(Cb + (size_t)m_hi * D + n) =
                        bfpair(acc[mt][nt][2], acc[mt][nt][3]);
            } else {
                float b0 = bias ? bias[n] : 0.f;
                float b1 = bias ? bias[n + 1] : 0.f;
                if (m_lo < NN)
                    *(float2*)(Cf + (size_t)m_lo * D + n) =
                        make_float2(acc[mt][nt][0] + b0, acc[mt][nt][1] + b1);
                if (m_hi < NN)
                    *(float2*)(Cf + (size_t)m_hi * D + n) =
                        make_float2(acc[mt][nt][2] + b0, acc[mt][nt][3] + b1);
            }
        }
    }
}

// ---- gemm1 split by dependency group ----
// g1a (s0): everything group-0 gather needs: h0, yb0, yb1  (uses x0, x1 only)
__global__ __launch_bounds__(256, 2) void gemm1a_tc() {
    switch (blockIdx.z) {
        case 0:  gemm_body<false>(g_xb,      g_WTb[0], g_bc1, g_h0, nullptr); break;
        case 1:  gemm_body<true >(g_xb,      g_WTb[2], nullptr, nullptr, g_yb0); break;
        default: gemm_body<true >(g_xb + ND, g_WTb[4], nullptr, nullptr, g_yb1); break;
    }
}
// g1b (s1): group-1 needs: h1, yb2, yb3  (uses x0, x1, x2)
__global__ __launch_bounds__(256, 2) void gemm1b_tc() {
    switch (blockIdx.z) {
        case 0:  gemm_body<false>(g_xb + ND,     g_WTb[1], g_bc1 + D, g_h1, nullptr); break;
        case 1:  gemm_body<true >(g_xb,          g_WTb[3], nullptr, nullptr, g_yb2); break;
        default: gemm_body<true >(g_xb + 2 * ND, g_WTb[5], nullptr, nullptr, g_yb3); break;
    }
}
// gemm2a (s0): o2 root + yb0' (both read hb0)
__global__ __launch_bounds__(256, 2) void gemm2a_tc() {
    if (blockIdx.z == 0) gemm_body<false>(g_hb0, g_WTb[6], g_bc2, g_o2, nullptr);
    else                 gemm_body<true >(g_hb0, g_WTb[7], nullptr, nullptr, g_yb0);
}
// gemm2b (s1): yb1' -> g_yb2 (dead after gather1_g1 in s1 order; no cross-stream WAR)
__global__ __launch_bounds__(256, 2) void gemm2b_tc() {
    gemm_body<true>(g_hb1, g_WTb[8], nullptr, nullptr, g_yb2);
}

// ---------------- bucket gather: one warp per dst node ----------------
__device__ __forceinline__ void accum_row(float* acc, const __nv_bfloat16* __restrict__ y0,
                                          const __nv_bfloat16* __restrict__ y1,
                                          int rec, int lane) {
    const __nv_bfloat16* yb = (rec < 0) ? y1 : y0;
    int src = rec & 0x7fffffff;
    uint4 v = *(const uint4*)(yb + (size_t)src * D + lane * 8);
    const __nv_bfloat162* p = (const __nv_bfloat162*)&v;
    float2 f0 = __bfloat1622float2(p[0]);
    float2 f1 = __bfloat1622float2(p[1]);
    float2 f2 = __bfloat1622float2(p[2]);
    float2 f3 = __bfloat1622float2(p[3]);
    acc[0] += f0.x; acc[1] += f0.y; acc[2] += f1.x; acc[3] += f1.y;
    acc[4] += f2.x; acc[5] += f2.y; acc[6] += f3.x; acc[7] += f3.y;
}

__device__ __forceinline__ void gather_accum(int grp, int node,
                                             const __nv_bfloat16* __restrict__ y0,
                                             const __nv_bfloat16* __restrict__ y1,
                                             float* acc, int lane) {
    const int* __restrict__ recs = g_rec[grp] + node * CAP;
    int cnt = g_cnt[grp][node];
    if (cnt > CAP) cnt = CAP;

    for (int base = 0; base < cnt; base += 32) {
        int m = cnt - base;
        if (m > 32) m = 32;
        int rec = 0;
        if (lane < m) rec = recs[base + lane];
        int j = 0;
        for (; j + 4 <= m; j += 4) {
            int r0 = __shfl_sync(0xFFFFFFFFu, rec, j);
            int r1 = __shfl_sync(0xFFFFFFFFu, rec, j + 1);
            int r2 = __shfl_sync(0xFFFFFFFFu, rec, j + 2);
            int r3 = __shfl_sync(0xFFFFFFFFu, rec, j + 3);
            accum_row(acc, y0, y1, r0, lane);
            accum_row(acc, y0, y1, r1, lane);
            accum_row(acc, y0, y1, r2, lane);
            accum_row(acc, y0, y1, r3, lane);
        }
        for (; j < m; j++) {
            int r = __shfl_sync(0xFFFFFFFFu, rec, j);
            accum_row(acc, y0, y1, r, lane);
        }
    }
}

// layer-1 gather for ONE group: h = root + agg; write bf16 relu(h)
template <int GRP>
__device__ __forceinline__ void gather1_body() {
    int node = (blockIdx.x * blockDim.x + threadIdx.x) >> 5;   // 0..NN-1
    int lane = threadIdx.x & 31;

    float acc[8] = {0.f, 0.f, 0.f, 0.f, 0.f, 0.f, 0.f, 0.f};
    if (GRP == 0) gather_accum(0, node, g_yb0, g_yb1, acc, lane);
    else          gather_accum(1, node, g_yb2, g_yb3, acc, lane);

    const float* rootp = (GRP == 0 ? g_h0 : g_h1) + (size_t)node * D + lane * 8;
    float4 a = *(const float4*)rootp;
    float4 b = *(const float4*)(rootp + 4);
    uint4 w;
    w.x = bfpair(fmaxf(a.x + acc[0], 0.f), fmaxf(a.y + acc[1], 0.f));
    w.y = bfpair(fmaxf(a.z + acc[2], 0.f), fmaxf(a.w + acc[3], 0.f));
    w.z = bfpair(fmaxf(b.x + acc[4], 0.f), fmaxf(b.y + acc[5], 0.f));
    w.w = bfpair(fmaxf(b.z + acc[6], 0.f), fmaxf(b.w + acc[7], 0.f));
    __nv_bfloat16* hb = GRP == 0 ? g_hb0 : g_hb1;
    *(uint4*)(hb + (size_t)node * D + lane * 8) = w;
}

__global__ void gather1_g0_kernel() { gather1_body<0>(); }
__global__ void gather1_g1_kernel() { gather1_body<1>(); }

// ---------------- fused layer-2 gather + loss ----------------
// tag0 rows from g_yb0 (gemm2a), tag1 rows from g_yb2 (gemm2b)
__global__ void gather2_loss_kernel(const int* __restrict__ y, float* __restrict__ out) {
    int gw   = (blockIdx.x * blockDim.x + threadIdx.x) >> 5;   // 0..19999
    int lane = threadIdx.x & 31;

    float acc[8] = {0.f, 0.f, 0.f, 0.f, 0.f, 0.f, 0.f, 0.f};
    gather_accum(0, gw, g_yb0, g_yb2, acc, lane);

    const float* rp = g_o2 + (size_t)gw * D + lane * 8;
    float4 a = *(const float4*)rp;
    float4 b = *(const float4*)(rp + 4);
    float v[8];
    v[0] = a.x + acc[0]; v[1] = a.y + acc[1]; v[2] = a.z + acc[2]; v[3] = a.w + acc[3];
    v[4] = b.x + acc[4]; v[5] = b.y + acc[5]; v[6] = b.z + acc[6]; v[7] = b.w + acc[7];

    float m = v[0];
#pragma unroll
    for (int i = 1; i < 8; i++) m = fmaxf(m, v[i]);
#pragma unroll
    for (int o = 16; o; o >>= 1) m = fmaxf(m, __shfl_xor_sync(0xFFFFFFFFu, m, o));

    float s = 0.0f;
#pragma unroll
    for (int i = 0; i < 8; i++) s += expf(v[i] - m);
#pragma unroll
    for (int o = 16; o; o >>= 1) s += __shfl_xor_sync(0xFFFFFFFFu, s, o);

    int yy = y[gw];
    float tv = v[0];
#pragma unroll
    for (int j = 1; j < 8; j++) tv = ((yy & 7) == j) ? v[j] : tv;
    float target = __shfl_sync(0xFFFFFFFFu, tv, yy >> 3);

    float nll = (m + logf(s)) - target;

    __shared__ float partial[8];
    if (lane == 0) partial[threadIdx.x >> 5] = nll;
    __syncthreads();
    if (threadIdx.x == 0) {
        float t = 0.0f;
#pragma unroll
        for (int i = 0; i < 8; i++) t += partial[i];
        atomicAdd(out, t * (1.0f / (float)NN));
    }
}

// ---------------- launch: R13 topology + front shave + no evH ----------------
extern "C" void kernel_launch(void* const* d_in, const int* in_sizes, int n_in,
                              void* d_out, int out_size) {
    const float* x      = (const float*)d_in[0];
    const int*   edges  = (const int*)d_in[1];
    const int*   y      = (const int*)d_in[2];
    const float* Wrel1  = (const float*)d_in[3];
    const float* brel1  = (const float*)d_in[4];
    const float* Wroot1 = (const float*)d_in[5];
    const float* Wrel2  = (const float*)d_in[6];
    const float* brel2  = (const float*)d_in[7];
    const float* Wroot2 = (const float*)d_in[8];
    float* out = (float*)d_out;

    static cudaStream_t s1 = nullptr;
    static cudaEvent_t evR, evP, evF, evG;
    if (!s1) {
        cudaStreamCreateWithFlags(&s1, cudaStreamNonBlocking);
        cudaEventCreateWithFlags(&evR, cudaEventDisableTiming);
        cudaEventCreateWithFlags(&evP, cudaEventDisableTiming);
        cudaEventCreateWithFlags(&evF, cudaEventDisableTiming);
        cudaEventCreateWithFlags(&evG, cudaEventDisableTiming);
    }
    cudaFuncSetAttribute(gemm1a_tc, cudaFuncAttributeMaxDynamicSharedMemorySize, SMEM_GEMM);
    cudaFuncSetAttribute(gemm1b_tc, cudaFuncAttributeMaxDynamicSharedMemorySize, SMEM_GEMM);
    cudaFuncSetAttribute(gemm2a_tc, cudaFuncAttributeMaxDynamicSharedMemorySize, SMEM_GEMM);
    cudaFuncSetAttribute(gemm2b_tc, cudaFuncAttributeMaxDynamicSharedMemorySize, SMEM_GEMM);

    const int MT = (NN + 127) / 128;   // 157 M-tiles
    cudaStream_t s0 = 0;

    // fork s1 from the capture origin
    cudaEventRecord(evR, s0);
    cudaStreamWaitEvent(s1, evR, 0);

    // s1: zero -> cvt(x2) -> fill   (all off the critical path)
    zero_cnt_kernel<<<(2 * NN + 255) / 256, 256, 0, s1>>>(out);
    cvt_kernel<2, 1><<<(ND / 4 + 255) / 256, 256, 0, s1>>>(x);
    fill_kernel<<<(4 * EE + 255) / 256, 256, 0, s1>>>(edges);
    cudaEventRecord(evF, s1);

    // s0: cvt(x0,x1) -> prep -> gemm1a      (shortest possible front)
    cvt_kernel<0, 2><<<(2 * ND / 4 + 255) / 256, 256, 0, s0>>>(x);
    prep_kernel<<<dim3(8, 8, 9), dim3(32, 8), 0, s0>>>(Wrel1, brel1, Wroot1,
                                                       Wrel2, brel2, Wroot2);
    cudaEventRecord(evP, s0);
    gemm1a_tc<<<dim3(MT, 2, 3), 256, SMEM_GEMM, s0>>>();

    // s1: gemm1b -> gather1_g1 -> gemm2b    (co-runs with s0 like R13)
    cudaStreamWaitEvent(s1, evP, 0);
    gemm1b_tc<<<dim3(MT, 2, 3), 256, SMEM_GEMM, s1>>>();
    gather1_g1_kernel<<<(NN * 32) / 256, 256, 0, s1>>>();
    gemm2b_tc<<<dim3(MT, 2, 1), 256, SMEM_GEMM, s1>>>();
    cudaEventRecord(evG, s1);

    // s0: gather1_g0 (needs fill) -> gemm2a
    cudaStreamWaitEvent(s0, evF, 0);
    gather1_g0_kernel<<<(NN * 32) / 256, 256, 0, s0>>>();
    gemm2a_tc<<<dim3(MT, 2, 2), 256, SMEM_GEMM, s0>>>();

    // s0: final fused gather+loss (joins s1; ends on capture origin)
    cudaStreamWaitEvent(s0, evG, 0);
    gather2_loss_kernel<<<NN / 8, 256, 0, s0>>>(y, out);
}